// round 10
// baseline (speedup 1.0000x reference)
#include <cuda_runtime.h>
#include <cuda_fp16.h>
#include <cstdint>

#define BATCH 32
#define HW    4096
#define NTOK  (BATCH * HW)
#define HH    64
#define WW    64

// ---------------- scratch ----------------
__device__ __half g_qkvh[(long)NTOK * 96];
__device__ __half g_m3h [(long)NTOK * 96];
__device__ __half g_m5h [(long)NTOK * 96];
__device__ float  g_vk  [BATCH * 12 * 72];
__device__ __half g_w1h [96 * 960];     // g-scaled qkv weights, fp16
__device__ __half g_w2h [960 * 96];
__device__ float  g_G   [3 * 96];       // per-seg sum g*W
__device__ float  g_U   [96];           // sum b*W

// ---------------- helpers ----------------
__device__ __forceinline__ uint32_t smem_u32(const void* p) {
    uint32_t a;
    asm("{ .reg .u64 t; cvta.to.shared.u64 t, %1; cvt.u32.u64 %0, t; }" : "=r"(a) : "l"(p));
    return a;
}
#define CP16(dst, src) asm volatile("cp.async.cg.shared.global [%0], [%1], 16;" :: "r"(dst), "l"(src))
#define CP_COMMIT()    asm volatile("cp.async.commit_group;" ::: "memory")
#define CP_WAIT0()     asm volatile("cp.async.wait_group 0;" ::: "memory")
#define CP_WAIT1()     asm volatile("cp.async.wait_group 1;" ::: "memory")

#define LDSM4(r, a) \
    asm volatile("ldmatrix.sync.aligned.m8n8.x4.shared.b16 {%0,%1,%2,%3}, [%4];" \
        : "=r"((r)[0]), "=r"((r)[1]), "=r"((r)[2]), "=r"((r)[3]) : "r"(a))
#define LDSM2(r, a) \
    asm volatile("ldmatrix.sync.aligned.m8n8.x2.shared.b16 {%0,%1}, [%2];" \
        : "=r"((r)[0]), "=r"((r)[1]) : "r"(a))
#define MMA16816(c, a, b) \
    asm volatile("mma.sync.aligned.m16n8k16.row.col.f32.f16.f16.f32 " \
        "{%0,%1,%2,%3}, {%4,%5,%6,%7}, {%8,%9}, {%0,%1,%2,%3};" \
        : "+f"((c)[0]), "+f"((c)[1]), "+f"((c)[2]), "+f"((c)[3]) \
        : "r"((a)[0]), "r"((a)[1]), "r"((a)[2]), "r"((a)[3]), "r"((b)[0]), "r"((b)[1]))

__device__ __forceinline__ uint32_t pkh(float a, float b) {
    __half2 h = __floats2half2_rn(a, b);
    return *reinterpret_cast<uint32_t*>(&h);
}
__device__ __forceinline__ void unpack8(uint4 u, float* f) {
    const __half2* hp = (const __half2*)&u;
#pragma unroll
    for (int i = 0; i < 4; i++) {
        float2 t = __half22float2(hp[i]);
        f[2*i] = t.x; f[2*i+1] = t.y;
    }
}

// ======================= prep: scaled weights + G/U + zero vk =======================
__global__ void prep_kernel(const float* __restrict__ w1, const float* __restrict__ w2,
                            const float* __restrict__ g1, const float* __restrict__ g2,
                            const float* __restrict__ g3, const float* __restrict__ b1,
                            const float* __restrict__ b2, const float* __restrict__ b3)
{
    if (blockIdx.x < 360) {
        int i = blockIdx.x * 256 + threadIdx.x;
        if (i < 96 * 960) {
            int k = i % 960;
            float gk = (k < 192) ? g1[k] : (k < 448) ? g2[k - 192] : g3[k - 448];
            g_w1h[i] = __float2half(w1[i] * gk);
            g_w2h[i] = __float2half(w2[i]);
        }
        if (i < BATCH * 12 * 72) g_vk[i] = 0.f;
    } else {
        int c = threadIdx.x;
        if (c < 96) {
            float G0 = 0.f, G1v = 0.f, G2v = 0.f, Uv = 0.f;
            for (int k = 0; k < 960; k++) {
                float w = w1[c * 960 + k];
                float gk, bk;
                if (k < 192)      { gk = g1[k];       bk = b1[k]; }
                else if (k < 448) { gk = g2[k - 192]; bk = b2[k - 192]; }
                else              { gk = g3[k - 448]; bk = b3[k - 448]; }
                float wg = w * gk;
                if (k < 192) G0 += wg; else if (k < 448) G1v += wg; else G2v += wg;
                Uv += w * bk;
            }
            g_G[c] = G0; g_G[96 + c] = G1v; g_G[192 + c] = G2v; g_U[c] = Uv;
        }
    }
}

// ======================= GEMM1: QKV with fully fused LN =======================
// smem: A[2][128][72]h, B[2][96][72]h, s_r[3][128], s_c[3][128], G[288], U[96]
#define QA(b)  ((b) * 18432)
#define QB(b)  (36864 + (b) * 13824)
#define QST    64512
#define QG     67584
#define QU     68736
#define G1_SMEM 69120

__global__ void __launch_bounds__(256) qkv_mm(const float* __restrict__ x1,
                                              const float* __restrict__ x2,
                                              const float* __restrict__ x3)
{
    extern __shared__ char sm[];
    uint32_t sb = smem_u32(sm);
    float* s_r = (float*)(sm + QST);            // [3][128] rstd
    float* s_c = (float*)(sm + QST + 1536);     // [3][128] -rstd*mean
    float* s_G = (float*)(sm + QG);
    float* s_U = (float*)(sm + QU);
    int tid = threadIdx.x, wid = tid >> 5, lane = tid & 31;
    int wm = wid >> 2, wn = wid & 3;
    long tok0 = (long)blockIdx.x * 128;

    for (int i = tid; i < 288; i += 256) s_G[i] = g_G[i];
    if (tid < 96) s_U[tid] = g_U[tid];

    float tot[4][3][4], tmp[4][3][4];
#pragma unroll
    for (int i = 0; i < 4; i++)
#pragma unroll
        for (int j = 0; j < 3; j++)
#pragma unroll
            for (int k = 0; k < 4; k++) { tot[i][j][k] = 0.f; tmp[i][j][k] = 0.f; }
    float ss[8], qq[8];
#pragma unroll
    for (int p = 0; p < 8; p++) { ss[p] = 0.f; qq[p] = 0.f; }
    float4 va[8];

    auto ldgA = [&](int c) {
        int kt = c * 64;
        const float* xs; int off, Cs;
        if (c < 3)      { xs = x1; off = 0;   Cs = 192; }
        else if (c < 7) { xs = x2; off = 192; Cs = 256; }
        else            { xs = x3; off = 448; Cs = 512; }
        int kl = kt - off;
#pragma unroll
        for (int p = 0; p < 8; p++) {
            int idx = tid + p * 256;
            int r = idx >> 4, q = idx & 15;
            va[p] = *(const float4*)(xs + (tok0 + r) * (long)Cs + kl + q * 4);
        }
    };
    auto stsA = [&](int buf) {
#pragma unroll
        for (int p = 0; p < 8; p++) {
            int idx = tid + p * 256;
            int r = idx >> 4, q = idx & 15;
            float4 v = va[p];
            ss[p] += v.x + v.y + v.z + v.w;
            qq[p] += v.x * v.x + v.y * v.y + v.z * v.z + v.w * v.w;
            *(uint2*)(sm + QA(buf) + (r * 72 + q * 4) * 2) =
                make_uint2(pkh(v.x, v.y), pkh(v.z, v.w));
        }
    };
    auto cpB = [&](int c, int buf) {
        int kt = c * 64;
#pragma unroll
        for (int p = 0; p < 3; p++) {
            int idx = tid + p * 256;
            int r = idx >> 3, q = idx & 7;
            CP16(sb + QB(buf) + (r * 72 + q * 8) * 2, g_w1h + r * 960 + kt + q * 8);
        }
    };
    auto finalize = [&](int sidx, float invC) {
        int sub = lane & 15;
#pragma unroll
        for (int p = 0; p < 8; p++) {
            float s = ss[p], q = qq[p];
#pragma unroll
            for (int off = 8; off > 0; off >>= 1) {
                s += __shfl_xor_sync(0xffffffffu, s, off);
                q += __shfl_xor_sync(0xffffffffu, q, off);
            }
            if (sub == 0) {
                int tok = (tid >> 4) + 16 * p;
                float m = s * invC;
                float rv = rsqrtf(q * invC - m * m + 1e-6f);
                s_r[sidx * 128 + tok] = rv;
                s_c[sidx * 128 + tok] = -rv * m;
            }
            ss[p] = 0.f; qq[p] = 0.f;
        }
    };
    auto fold = [&](int sidx) {
#pragma unroll
        for (int mi = 0; mi < 4; mi++) {
            int row0 = wm * 64 + mi * 16 + (lane >> 2);
            float r0 = s_r[sidx * 128 + row0];
            float r1 = s_r[sidx * 128 + row0 + 8];
#pragma unroll
            for (int ni = 0; ni < 3; ni++) {
                tot[mi][ni][0] += r0 * tmp[mi][ni][0];
                tot[mi][ni][1] += r0 * tmp[mi][ni][1];
                tot[mi][ni][2] += r1 * tmp[mi][ni][2];
                tot[mi][ni][3] += r1 * tmp[mi][ni][3];
                tmp[mi][ni][0] = 0.f; tmp[mi][ni][1] = 0.f;
                tmp[mi][ni][2] = 0.f; tmp[mi][ni][3] = 0.f;
            }
        }
    };

    // prologue
    ldgA(0); stsA(0);
    cpB(0, 0); CP_COMMIT();
    CP_WAIT0();
    __syncthreads();

    for (int c = 0; c < 15; c++) {
        int buf = c & 1;
        if (c + 1 < 15) { cpB(c + 1, 1 - buf); CP_COMMIT(); ldgA(c + 1); }

        uint32_t abase = sb + QA(buf);
        uint32_t bbase = sb + QB(buf);
#pragma unroll
        for (int ks = 0; ks < 4; ks++) {
            uint32_t a[4][4], b[3][2];
#pragma unroll
            for (int mi = 0; mi < 4; mi++) {
                uint32_t addr = abase + ((wm * 64 + mi * 16 + (lane & 15)) * 72
                                         + ks * 16 + (lane >> 4) * 8) * 2;
                LDSM4(a[mi], addr);
            }
#pragma unroll
            for (int ni = 0; ni < 3; ni++) {
                uint32_t addr = bbase + ((wn * 24 + ni * 8 + (lane & 7)) * 72
                                         + ks * 16 + ((lane >> 3) & 1) * 8) * 2;
                LDSM2(b[ni], addr);
            }
#pragma unroll
            for (int mi = 0; mi < 4; mi++)
#pragma unroll
                for (int ni = 0; ni < 3; ni++) MMA16816(tmp[mi][ni], a[mi], b[ni]);
        }

        if (c + 1 < 15) {
            stsA(1 - buf);
            if (c == 1)  finalize(0, 1.0f / 192.f);
            if (c == 5)  finalize(1, 1.0f / 256.f);
            if (c == 13) finalize(2, 1.0f / 512.f);
            CP_WAIT0();
            __syncthreads();
        }
        if (c == 2) fold(0);
        if (c == 6) fold(1);
    }
    fold(2);

    // epilogue: + segment corrections + U, pack fp16
#pragma unroll
    for (int mi = 0; mi < 4; mi++) {
        int row0 = wm * 64 + mi * 16 + (lane >> 2);
        float c00 = s_c[row0],       c01 = s_c[128 + row0],       c02 = s_c[256 + row0];
        float c10 = s_c[row0 + 8],   c11 = s_c[128 + row0 + 8],   c12 = s_c[256 + row0 + 8];
        long t0 = tok0 + row0, t1 = t0 + 8;
#pragma unroll
        for (int ni = 0; ni < 3; ni++) {
            int ch = wn * 24 + ni * 8 + (lane & 3) * 2;
            float Ga0 = s_G[ch],     Ga1 = s_G[ch + 1];
            float Gb0 = s_G[96+ch],  Gb1 = s_G[96+ch+1];
            float Gc0 = s_G[192+ch], Gc1 = s_G[192+ch+1];
            float U0 = s_U[ch], U1 = s_U[ch + 1];
            float v00 = tot[mi][ni][0] + c00*Ga0 + c01*Gb0 + c02*Gc0 + U0;
            float v01 = tot[mi][ni][1] + c00*Ga1 + c01*Gb1 + c02*Gc1 + U1;
            float v10 = tot[mi][ni][2] + c10*Ga0 + c11*Gb0 + c12*Gc0 + U0;
            float v11 = tot[mi][ni][3] + c10*Ga1 + c11*Gb1 + c12*Gc1 + U1;
            *(uint32_t*)(g_qkvh + t0 * 96 + ch) = pkh(v00, v01);
            *(uint32_t*)(g_qkvh + t1 * 96 + ch) = pkh(v10, v11);
        }
    }
}

// ======================= conv (fp16 IO) =======================
__global__ void __launch_bounds__(256, 2) conv_kernel(
    const float* __restrict__ dw3, const float* __restrict__ pw3,
    const float* __restrict__ dw5, const float* __restrict__ pw5)
{
    int b  = blockIdx.z;
    int g  = blockIdx.y;
    int r0 = blockIdx.x * 16;
    __shared__ float tile[8][20][69];
    __shared__ float s_w3[8][9], s_w5[8][25], s_p3[8][8], s_p5[8][8];
    int tid = threadIdx.x, lane = tid & 31;
    long sp = (long)b * HW;

    for (int idx = tid; idx < 20 * 68; idx += 256) {
        int r = idx / 68, col = idx % 68;
        int gr = r0 + r - 2, gc = col - 2;
        float f[8] = {0.f,0.f,0.f,0.f,0.f,0.f,0.f,0.f};
        if (gr >= 0 && gr < HH && gc >= 0 && gc < WW) {
            uint4 u = *(const uint4*)(g_qkvh + (sp + gr * WW + gc) * 96 + g * 8);
            unpack8(u, f);
        }
#pragma unroll
        for (int i = 0; i < 8; i++) tile[i][r][col] = f[i];
    }
    if (tid < 72)  s_w3[tid/9][tid%9]   = dw3[(g*8 + tid/9)*9  + tid%9];
    if (tid < 200) s_w5[tid/25][tid%25] = dw5[(g*8 + tid/25)*25 + tid%25];
    if (tid < 64)  { s_p3[tid/8][tid%8] = pw3[(g*8 + tid/8)*8 + tid%8];
                     s_p5[tid/8][tid%8] = pw5[(g*8 + tid/8)*8 + tid%8]; }
    __syncthreads();

    int ch = tid & 7;
    int colbase = tid >> 3;
    float w5r[25], w3r[9], p3r[8], p5r[8];
#pragma unroll
    for (int i = 0; i < 25; i++) w5r[i] = s_w5[ch][i];
#pragma unroll
    for (int i = 0; i < 9;  i++) w3r[i] = s_w3[ch][i];
#pragma unroll
    for (int i = 0; i < 8;  i++) { p3r[i] = s_p3[ch][i]; p5r[i] = s_p5[ch][i]; }

#pragma unroll
    for (int cp = 0; cp < 2; cp++) {
        int col = colbase + cp * 32;
        float rb[5][5];
#pragma unroll
        for (int rr = 0; rr < 4; rr++)
#pragma unroll
            for (int cc = 0; cc < 5; cc++) rb[rr][cc] = tile[ch][rr][col + cc];
#pragma unroll
        for (int r = 0; r < 16; r++) {
            int s4 = (r + 4) % 5;
#pragma unroll
            for (int cc = 0; cc < 5; cc++) rb[s4][cc] = tile[ch][r + 4][col + cc];
            float d5 = 0.f, d3 = 0.f;
#pragma unroll
            for (int ky = 0; ky < 5; ky++) {
                int ssn = (r + ky) % 5;
#pragma unroll
                for (int cc = 0; cc < 5; cc++) d5 += w5r[ky*5+cc] * rb[ssn][cc];
            }
#pragma unroll
            for (int ky = 0; ky < 3; ky++) {
                int ssn = (r + 1 + ky) % 5;
#pragma unroll
                for (int cc = 0; cc < 3; cc++) d3 += w3r[ky*3+cc] * rb[ssn][cc + 1];
            }
            float o3 = 0.f, o5 = 0.f;
#pragma unroll
            for (int i = 0; i < 8; i++) {
                int src = (lane & 24) | i;
                o3 += p3r[i] * __shfl_sync(0xffffffffu, d3, src);
                o5 += p5r[i] * __shfl_sync(0xffffffffu, d5, src);
            }
            long ob = (sp + (long)(r0 + r) * WW + col) * 96 + g * 8 + ch;
            g_m3h[ob] = __float2half(o3);
            g_m5h[ob] = __float2half(o5);
        }
    }
}

// ======================= vk =======================
__global__ void vk_kernel()
{
    int g = blockIdx.x, b = blockIdx.y;
    int n0 = blockIdx.z * 1024;
    const __half* ten = (g < 4) ? g_qkvh : (g < 8) ? g_m3h : g_m5h;
    int base = 24 * (g & 3);

    float acc[72];
#pragma unroll
    for (int i = 0; i < 72; i++) acc[i] = 0.f;

    for (int n = n0 + threadIdx.x; n < n0 + 1024; n += 256) {
        const __half* row = ten + ((long)b * HW + n) * 96 + base;
        float kv[8], vv[8];
        unpack8(*(const uint4*)(row + 8),  kv);
        unpack8(*(const uint4*)(row + 16), vv);
#pragma unroll
        for (int e = 0; e < 8; e++) kv[e] = fmaxf(kv[e], 0.f);
#pragma unroll
        for (int d = 0; d < 8; d++)
#pragma unroll
            for (int e = 0; e < 8; e++) acc[d * 8 + e] += vv[d] * kv[e];
#pragma unroll
        for (int e = 0; e < 8; e++) acc[64 + e] += kv[e];
    }

    __shared__ float red[8][72];
    int lane = threadIdx.x & 31, warp = threadIdx.x >> 5;
#pragma unroll
    for (int i = 0; i < 72; i++) {
        float v = acc[i];
#pragma unroll
        for (int off = 16; off > 0; off >>= 1) v += __shfl_xor_sync(0xffffffffu, v, off);
        if (lane == 0) red[warp][i] = v;
    }
    __syncthreads();
    if (threadIdx.x < 72) {
        float s = 0.f;
#pragma unroll
        for (int w = 0; w < 8; w++) s += red[w][threadIdx.x];
        atomicAdd(&g_vk[(b * 12 + g) * 72 + threadIdx.x], s);
    }
}

// ======================= GEMM2: proj =======================
#define P_AS      0
#define P_BS(b)   (13312 + (b) * 19968)
#define P_ST      53248
#define P_SC      78848
#define P_BI      82688
#define P_VK      86528
#define P_SMEM    89984
#define SEG2 25165824L
#define SEG3 58720256L

__global__ void __launch_bounds__(256, 2) proj_mm(
    const float* __restrict__ bn_g, const float* __restrict__ bn_b,
    const float* __restrict__ bn_m, const float* __restrict__ bn_v,
    const float* __restrict__ x1, const float* __restrict__ x2, const float* __restrict__ x3,
    float* __restrict__ out)
{
    extern __shared__ char sm[];
    uint32_t sb = smem_u32(sm);
    int tid = threadIdx.x, wid = tid >> 5, lane = tid & 31;
    int wm = wid >> 2, wn = wid & 3;
    long tok0 = (long)blockIdx.x * 64;
    int bidx = blockIdx.x >> 6;

    float* s_sc = (float*)(sm + P_SC);
    float* s_bi = (float*)(sm + P_BI);
    float* s_vk = (float*)(sm + P_VK);
    float* st   = (float*)(sm + P_ST);
    for (int c = tid; c < 960; c += 256) {
        float scv = bn_g[c] * rsqrtf(bn_v[c] + 1e-5f);
        s_sc[c] = scv;
        s_bi[c] = bn_b[c] - bn_m[c] * scv;
    }
    for (int i = tid; i < 864; i += 256) s_vk[i] = g_vk[bidx * 864 + i];
    __syncthreads();

    {
        int tok = tid >> 2;
        int quarter = tid & 3;
        long tokG = tok0 + tok;
#pragma unroll
        for (int gg0 = 0; gg0 < 3; gg0++) {
            int gg = quarter * 3 + gg0;
            const __half* ten = (gg < 4) ? g_qkvh : (gg < 8) ? g_m3h : g_m5h;
            int base = 24 * (gg & 3);
            float q[8];
            unpack8(*(const uint4*)(ten + tokG * 96 + base), q);
#pragma unroll
            for (int e = 0; e < 8; e++) q[e] = fmaxf(q[e], 0.f);
            const float* vkp = s_vk + gg * 72;
            float den = 1e-15f;
#pragma unroll
            for (int e = 0; e < 8; e++) den += vkp[64 + e] * q[e];
            float inv = 1.0f / den;
            float o[8];
#pragma unroll
            for (int d = 0; d < 8; d++) {
                float num = 0.f;
#pragma unroll
                for (int e = 0; e < 8; e++) num += vkp[d * 8 + e] * q[e];
                o[d] = num * inv;
            }
            uint4 pack;
            pack.x = pkh(o[0], o[1]); pack.y = pkh(o[2], o[3]);
            pack.z = pkh(o[4], o[5]); pack.w = pkh(o[6], o[7]);
            *(uint4*)(sm + P_AS + (tok * 104 + gg * 8) * 2) = pack;
        }
    }

    auto cpB = [&](int t, int buf) {
        int o0 = t * 96;
#pragma unroll
        for (int p = 0; p < 5; p++) {
            int idx = tid + p * 256;
            if (idx < 1152) {
                int r = idx / 12, q = idx % 12;
                CP16(sb + P_BS(buf) + (r * 104 + q * 8) * 2, g_w2h + (long)(o0 + r) * 96 + q * 8);
            }
        }
    };
    __syncthreads();
    cpB(0, 0); CP_COMMIT();

    for (int t = 0; t < 10; t++) {
        int buf = t & 1;
        int o0 = t * 96;
        if (t + 1 < 10) { cpB(t + 1, 1 - buf); CP_COMMIT(); }
        if (t + 1 < 10) CP_WAIT1(); else CP_WAIT0();
        __syncthreads();

        float acc[2][3][4];
#pragma unroll
        for (int i = 0; i < 2; i++)
#pragma unroll
            for (int j = 0; j < 3; j++)
#pragma unroll
                for (int k = 0; k < 4; k++) acc[i][j][k] = 0.f;

        uint32_t abase = sb + P_AS;
        uint32_t bbase = sb + P_BS(buf);
#pragma unroll
        for (int ks = 0; ks < 6; ks++) {
            uint32_t a[2][4], b[3][2];
#pragma unroll
            for (int mi = 0; mi < 2; mi++) {
                uint32_t addr = abase + ((wm * 32 + mi * 16 + (lane & 15)) * 104
                                         + ks * 16 + (lane >> 4) * 8) * 2;
                LDSM4(a[mi], addr);
            }
#pragma unroll
            for (int ni = 0; ni < 3; ni++) {
                uint32_t addr = bbase + ((wn * 24 + ni * 8 + (lane & 7)) * 104
                                         + ks * 16 + ((lane >> 3) & 1) * 8) * 2;
                LDSM2(b[ni], addr);
            }
#pragma unroll
            for (int mi = 0; mi < 2; mi++)
#pragma unroll
                for (int ni = 0; ni < 3; ni++) MMA16816(acc[mi][ni], a[mi], b[ni]);
        }

#pragma unroll
        for (int mi = 0; mi < 2; mi++)
#pragma unroll
            for (int ni = 0; ni < 3; ni++)
#pragma unroll
                for (int h = 0; h < 2; h++) {
                    int tok = wm * 32 + mi * 16 + (lane >> 2) + h * 8;
                    int chl = wn * 24 + ni * 8 + (lane & 3) * 2;
                    *(float2*)(st + tok * 100 + chl) =
                        make_float2(acc[mi][ni][h*2+0], acc[mi][ni][h*2+1]);
                }
        __syncthreads();

#pragma unroll
        for (int p = 0; p < 6; p++) {
            int idx = tid + p * 256;
            int tok = idx / 24, c4 = (idx % 24) * 4;
            long tokG = tok0 + tok;
            int ch = o0 + c4;
            float4 v  = *(const float4*)(st + tok * 100 + c4);
            float4 sc = *(const float4*)(s_sc + ch);
            float4 bi = *(const float4*)(s_bi + ch);
            const float* xp; float* op;
            if (ch < 192)      { long a = tokG * 192 + ch;         xp = x1 + a; op = out + a; }
            else if (ch < 448) { long a = tokG * 256 + (ch - 192); xp = x2 + a; op = out + SEG2 + a; }
            else               { long a = tokG * 512 + (ch - 448); xp = x3 + a; op = out + SEG3 + a; }
            float4 xv = *(const float4*)xp;
            float4 o4;
            o4.x = v.x * sc.x + bi.x + xv.x;
            o4.y = v.y * sc.y + bi.y + xv.y;
            o4.z = v.z * sc.z + bi.z + xv.z;
            o4.w = v.w * sc.w + bi.w + xv.w;
            *(float4*)op = o4;
        }
        __syncthreads();
    }
}

// ======================= launch =======================
extern "C" void kernel_launch(void* const* d_in, const int* in_sizes, int n_in,
                              void* d_out, int out_size)
{
    const float *x1, *g1, *b1, *x2, *g2, *b2, *x3, *g3, *b3;
    if (in_sizes[1] < 100000) {
        x1 = (const float*)d_in[0]; g1 = (const float*)d_in[1]; b1 = (const float*)d_in[2];
        x2 = (const float*)d_in[3]; g2 = (const float*)d_in[4]; b2 = (const float*)d_in[5];
        x3 = (const float*)d_in[6]; g3 = (const float*)d_in[7]; b3 = (const float*)d_in[8];
    } else {
        x1 = (const float*)d_in[0]; x2 = (const float*)d_in[1]; x3 = (const float*)d_in[2];
        g1 = (const float*)d_in[3]; b1 = (const float*)d_in[4];
        g2 = (const float*)d_in[5]; b2 = (const float*)d_in[6];
        g3 = (const float*)d_in[7]; b3 = (const float*)d_in[8];
    }
    const float* qkv_w  = (const float*)d_in[9];
    const float* dw3    = (const float*)d_in[10];
    const float* pw3    = (const float*)d_in[11];
    const float* dw5    = (const float*)d_in[12];
    const float* pw5    = (const float*)d_in[13];
    const float* proj_w = (const float*)d_in[14];
    const float* bn_g   = (const float*)d_in[15];
    const float* bn_b   = (const float*)d_in[16];
    const float* bn_m   = (const float*)d_in[17];
    const float* bn_v   = (const float*)d_in[18];
    float* out = (float*)d_out;

    cudaFuncSetAttribute(qkv_mm,  cudaFuncAttributeMaxDynamicSharedMemorySize, G1_SMEM);
    cudaFuncSetAttribute(proj_mm, cudaFuncAttributeMaxDynamicSharedMemorySize, P_SMEM);

    prep_kernel<<<361, 256>>>(qkv_w, proj_w, g1, g2, g3, b1, b2, b3);        // 1
    qkv_mm<<<NTOK / 128, 256, G1_SMEM>>>(x1, x2, x3);                        // 2
    conv_kernel<<<dim3(4, 12, BATCH), 256>>>(dw3, pw3, dw5, pw5);            // 3
    vk_kernel<<<dim3(12, BATCH, 4), 256>>>();                                // 4
    proj_mm<<<NTOK / 64, 256, P_SMEM>>>(bn_g, bn_b, bn_m, bn_v, x1, x2, x3, out);  // 5
}

// round 11
// speedup vs baseline: 1.4627x; 1.4627x over previous
#include <cuda_runtime.h>
#include <cuda_fp16.h>
#include <cstdint>

#define BATCH 32
#define HW    4096
#define NTOK  (BATCH * HW)
#define HH    64
#define WW    64

// ---------------- scratch ----------------
__device__ __half g_xh  [(long)NTOK * 960];
__device__ __half g_qkvh[(long)NTOK * 96];
__device__ __half g_m3h [(long)NTOK * 96];
__device__ __half g_m5h [(long)NTOK * 96];
__device__ float  g_vk  [BATCH * 12 * 72];
__device__ __half g_w1h [96 * 960];
__device__ __half g_w2h [960 * 96];

// ---------------- helpers ----------------
__device__ __forceinline__ uint32_t smem_u32(const void* p) {
    uint32_t a;
    asm("{ .reg .u64 t; cvta.to.shared.u64 t, %1; cvt.u32.u64 %0, t; }" : "=r"(a) : "l"(p));
    return a;
}
#define CP16(dst, src) asm volatile("cp.async.cg.shared.global [%0], [%1], 16;" :: "r"(dst), "l"(src))
#define CP_COMMIT()    asm volatile("cp.async.commit_group;" ::: "memory")
#define CP_WAIT0()     asm volatile("cp.async.wait_group 0;" ::: "memory")
#define CP_WAIT1()     asm volatile("cp.async.wait_group 1;" ::: "memory")

#define LDSM4(r, a) \
    asm volatile("ldmatrix.sync.aligned.m8n8.x4.shared.b16 {%0,%1,%2,%3}, [%4];" \
        : "=r"((r)[0]), "=r"((r)[1]), "=r"((r)[2]), "=r"((r)[3]) : "r"(a))
#define LDSM2(r, a) \
    asm volatile("ldmatrix.sync.aligned.m8n8.x2.shared.b16 {%0,%1}, [%2];" \
        : "=r"((r)[0]), "=r"((r)[1]) : "r"(a))
#define MMA16816(c, a, b) \
    asm volatile("mma.sync.aligned.m16n8k16.row.col.f32.f16.f16.f32 " \
        "{%0,%1,%2,%3}, {%4,%5,%6,%7}, {%8,%9}, {%0,%1,%2,%3};" \
        : "+f"((c)[0]), "+f"((c)[1]), "+f"((c)[2]), "+f"((c)[3]) \
        : "r"((a)[0]), "r"((a)[1]), "r"((a)[2]), "r"((a)[3]), "r"((b)[0]), "r"((b)[1]))

__device__ __forceinline__ uint32_t pkh(float a, float b) {
    __half2 h = __floats2half2_rn(a, b);
    return *reinterpret_cast<uint32_t*>(&h);
}
__device__ __forceinline__ void unpack8(uint4 u, float* f) {
    const __half2* hp = (const __half2*)&u;
#pragma unroll
    for (int i = 0; i < 4; i++) {
        float2 t = __half22float2(hp[i]);
        f[2*i] = t.x; f[2*i+1] = t.y;
    }
}

// ======================= lnx (+ fused weight prep in first 360 blocks) =======================
__global__ void __launch_bounds__(256) lnx_kernel(
    const float* __restrict__ x1, const float* __restrict__ g1, const float* __restrict__ b1,
    const float* __restrict__ x2, const float* __restrict__ g2, const float* __restrict__ b2,
    const float* __restrict__ x3, const float* __restrict__ g3, const float* __restrict__ b3,
    const float* __restrict__ w1, const float* __restrict__ w2)
{
    int tid = threadIdx.x;
    if (blockIdx.x < 360) {
        int i = blockIdx.x * 256 + tid;
        if (i < 96 * 960) {
            g_w1h[i] = __float2half(w1[i]);
            g_w2h[i] = __float2half(w2[i]);
        }
        if (i < BATCH * 12 * 72) g_vk[i] = 0.f;
    }

    long t = (long)blockIdx.x * 8 + (tid >> 5);
    int lane = tid & 31;
    float2 a1[3], a2[4], a3[8];
    const float* p1 = x1 + t * 192;
    const float* p2 = x2 + t * 256;
    const float* p3 = x3 + t * 512;
#pragma unroll
    for (int r = 0; r < 3; r++) a1[r] = *(const float2*)(p1 + 2 * lane + 64 * r);
#pragma unroll
    for (int r = 0; r < 4; r++) a2[r] = *(const float2*)(p2 + 2 * lane + 64 * r);
#pragma unroll
    for (int r = 0; r < 8; r++) a3[r] = *(const float2*)(p3 + 2 * lane + 64 * r);

    float s1 = 0.f, q1 = 0.f, s2 = 0.f, q2 = 0.f, s3 = 0.f, q3 = 0.f;
#pragma unroll
    for (int r = 0; r < 3; r++) { s1 += a1[r].x + a1[r].y; q1 += a1[r].x*a1[r].x + a1[r].y*a1[r].y; }
#pragma unroll
    for (int r = 0; r < 4; r++) { s2 += a2[r].x + a2[r].y; q2 += a2[r].x*a2[r].x + a2[r].y*a2[r].y; }
#pragma unroll
    for (int r = 0; r < 8; r++) { s3 += a3[r].x + a3[r].y; q3 += a3[r].x*a3[r].x + a3[r].y*a3[r].y; }
#pragma unroll
    for (int off = 16; off > 0; off >>= 1) {
        s1 += __shfl_xor_sync(0xffffffffu, s1, off);
        q1 += __shfl_xor_sync(0xffffffffu, q1, off);
        s2 += __shfl_xor_sync(0xffffffffu, s2, off);
        q2 += __shfl_xor_sync(0xffffffffu, q2, off);
        s3 += __shfl_xor_sync(0xffffffffu, s3, off);
        q3 += __shfl_xor_sync(0xffffffffu, q3, off);
    }
    float m1 = s1 / 192.f, r1 = rsqrtf(q1 / 192.f - m1 * m1 + 1e-6f);
    float m2 = s2 / 256.f, r2 = rsqrtf(q2 / 256.f - m2 * m2 + 1e-6f);
    float m3v = s3 / 512.f, r3 = rsqrtf(q3 / 512.f - m3v * m3v + 1e-6f);

    __half* dst = g_xh + t * 960;
#pragma unroll
    for (int r = 0; r < 3; r++) {
        int c = 2 * lane + 64 * r;
        float2 gg = *(const float2*)(g1 + c), bb = *(const float2*)(b1 + c);
        *(uint32_t*)(dst + c) = pkh((a1[r].x - m1) * r1 * gg.x + bb.x, (a1[r].y - m1) * r1 * gg.y + bb.y);
    }
#pragma unroll
    for (int r = 0; r < 4; r++) {
        int c = 2 * lane + 64 * r;
        float2 gg = *(const float2*)(g2 + c), bb = *(const float2*)(b2 + c);
        *(uint32_t*)(dst + 192 + c) = pkh((a2[r].x - m2) * r2 * gg.x + bb.x, (a2[r].y - m2) * r2 * gg.y + bb.y);
    }
#pragma unroll
    for (int r = 0; r < 8; r++) {
        int c = 2 * lane + 64 * r;
        float2 gg = *(const float2*)(g3 + c), bb = *(const float2*)(b3 + c);
        *(uint32_t*)(dst + 448 + c) = pkh((a3[r].x - m3v) * r3 * gg.x + bb.x, (a3[r].y - m3v) * r3 * gg.y + bb.y);
    }
}

// ======================= GEMM1: QKV (3-stage cp.async) =======================
#define G1_AS(b) ((b) * 18432)
#define G1_BS(b) (55296 + (b) * 13824)
#define G1_SMEM  96768

__global__ void __launch_bounds__(256) qkv_mm()
{
    extern __shared__ char sm[];
    uint32_t sb = smem_u32(sm);
    int tid = threadIdx.x, wid = tid >> 5, lane = tid & 31;
    int wm = wid >> 2, wn = wid & 3;
    long tok0 = (long)blockIdx.x * 128;

    float acc[4][3][4];
#pragma unroll
    for (int i = 0; i < 4; i++)
#pragma unroll
        for (int j = 0; j < 3; j++)
#pragma unroll
            for (int k = 0; k < 4; k++) acc[i][j][k] = 0.f;

    auto cpAB = [&](int c, int buf) {
        int kt = c * 64;
#pragma unroll
        for (int p = 0; p < 4; p++) {
            int idx = tid + p * 256;
            int r = idx >> 3, q = idx & 7;
            CP16(sb + G1_AS(buf) + (r * 72 + q * 8) * 2, g_xh + (tok0 + r) * 960 + kt + q * 8);
        }
#pragma unroll
        for (int p = 0; p < 3; p++) {
            int idx = tid + p * 256;
            int r = idx >> 3, q = idx & 7;
            CP16(sb + G1_BS(buf) + (r * 72 + q * 8) * 2, g_w1h + r * 960 + kt + q * 8);
        }
    };

    cpAB(0, 0); CP_COMMIT();
    cpAB(1, 1); CP_COMMIT();

    for (int c = 0; c < 15; c++) {
        if (c < 14) CP_WAIT1(); else CP_WAIT0();
        __syncthreads();
        if (c + 2 < 15) { cpAB(c + 2, (c + 2) % 3); CP_COMMIT(); }

        int buf = c % 3;
        uint32_t abase = sb + G1_AS(buf);
        uint32_t bbase = sb + G1_BS(buf);
#pragma unroll
        for (int ks = 0; ks < 4; ks++) {
            uint32_t a[4][4], b[3][2];
#pragma unroll
            for (int mi = 0; mi < 4; mi++) {
                uint32_t addr = abase + ((wm * 64 + mi * 16 + (lane & 15)) * 72
                                         + ks * 16 + (lane >> 4) * 8) * 2;
                LDSM4(a[mi], addr);
            }
#pragma unroll
            for (int ni = 0; ni < 3; ni++) {
                uint32_t addr = bbase + ((wn * 24 + ni * 8 + (lane & 7)) * 72
                                         + ks * 16 + ((lane >> 3) & 1) * 8) * 2;
                LDSM2(b[ni], addr);
            }
#pragma unroll
            for (int mi = 0; mi < 4; mi++)
#pragma unroll
                for (int ni = 0; ni < 3; ni++) MMA16816(acc[mi][ni], a[mi], b[ni]);
        }
    }

#pragma unroll
    for (int mi = 0; mi < 4; mi++) {
        long tokA = tok0 + wm * 64 + mi * 16 + (lane >> 2);
#pragma unroll
        for (int ni = 0; ni < 3; ni++) {
            int ch = wn * 24 + ni * 8 + (lane & 3) * 2;
            *(uint32_t*)(g_qkvh + tokA * 96 + ch)       = pkh(acc[mi][ni][0], acc[mi][ni][1]);
            *(uint32_t*)(g_qkvh + (tokA + 8) * 96 + ch) = pkh(acc[mi][ni][2], acc[mi][ni][3]);
        }
    }
}

// ======================= conv (fp16 IO) =======================
__global__ void __launch_bounds__(256, 2) conv_kernel(
    const float* __restrict__ dw3, const float* __restrict__ pw3,
    const float* __restrict__ dw5, const float* __restrict__ pw5)
{
    int b  = blockIdx.z;
    int g  = blockIdx.y;
    int r0 = blockIdx.x * 16;
    __shared__ float tile[8][20][69];
    __shared__ float s_w3[8][9], s_w5[8][25], s_p3[8][8], s_p5[8][8];
    int tid = threadIdx.x, lane = tid & 31;
    long sp = (long)b * HW;

    for (int idx = tid; idx < 20 * 68; idx += 256) {
        int r = idx / 68, col = idx % 68;
        int gr = r0 + r - 2, gc = col - 2;
        float f[8] = {0.f,0.f,0.f,0.f,0.f,0.f,0.f,0.f};
        if (gr >= 0 && gr < HH && gc >= 0 && gc < WW) {
            uint4 u = *(const uint4*)(g_qkvh + (sp + gr * WW + gc) * 96 + g * 8);
            unpack8(u, f);
        }
#pragma unroll
        for (int i = 0; i < 8; i++) tile[i][r][col] = f[i];
    }
    if (tid < 72)  s_w3[tid/9][tid%9]   = dw3[(g*8 + tid/9)*9  + tid%9];
    if (tid < 200) s_w5[tid/25][tid%25] = dw5[(g*8 + tid/25)*25 + tid%25];
    if (tid < 64)  { s_p3[tid/8][tid%8] = pw3[(g*8 + tid/8)*8 + tid%8];
                     s_p5[tid/8][tid%8] = pw5[(g*8 + tid/8)*8 + tid%8]; }
    __syncthreads();

    int ch = tid & 7;
    int colbase = tid >> 3;
    float w5r[25], w3r[9], p3r[8], p5r[8];
#pragma unroll
    for (int i = 0; i < 25; i++) w5r[i] = s_w5[ch][i];
#pragma unroll
    for (int i = 0; i < 9;  i++) w3r[i] = s_w3[ch][i];
#pragma unroll
    for (int i = 0; i < 8;  i++) { p3r[i] = s_p3[ch][i]; p5r[i] = s_p5[ch][i]; }

#pragma unroll
    for (int cp = 0; cp < 2; cp++) {
        int col = colbase + cp * 32;
        float rb[5][5];
#pragma unroll
        for (int rr = 0; rr < 4; rr++)
#pragma unroll
            for (int cc = 0; cc < 5; cc++) rb[rr][cc] = tile[ch][rr][col + cc];
#pragma unroll
        for (int r = 0; r < 16; r++) {
            int s4 = (r + 4) % 5;
#pragma unroll
            for (int cc = 0; cc < 5; cc++) rb[s4][cc] = tile[ch][r + 4][col + cc];
            float d5 = 0.f, d3 = 0.f;
#pragma unroll
            for (int ky = 0; ky < 5; ky++) {
                int ssn = (r + ky) % 5;
#pragma unroll
                for (int cc = 0; cc < 5; cc++) d5 += w5r[ky*5+cc] * rb[ssn][cc];
            }
#pragma unroll
            for (int ky = 0; ky < 3; ky++) {
                int ssn = (r + 1 + ky) % 5;
#pragma unroll
                for (int cc = 0; cc < 3; cc++) d3 += w3r[ky*3+cc] * rb[ssn][cc + 1];
            }
            float o3 = 0.f, o5 = 0.f;
#pragma unroll
            for (int i = 0; i < 8; i++) {
                int src = (lane & 24) | i;
                o3 += p3r[i] * __shfl_sync(0xffffffffu, d3, src);
                o5 += p5r[i] * __shfl_sync(0xffffffffu, d5, src);
            }
            long ob = (sp + (long)(r0 + r) * WW + col) * 96 + g * 8 + ch;
            g_m3h[ob] = __float2half(o3);
            g_m5h[ob] = __float2half(o5);
        }
    }
}

// ======================= vk =======================
__global__ void vk_kernel()
{
    int g = blockIdx.x, b = blockIdx.y;
    int n0 = blockIdx.z * 1024;
    const __half* ten = (g < 4) ? g_qkvh : (g < 8) ? g_m3h : g_m5h;
    int base = 24 * (g & 3);

    float acc[72];
#pragma unroll
    for (int i = 0; i < 72; i++) acc[i] = 0.f;

    for (int n = n0 + threadIdx.x; n < n0 + 1024; n += 256) {
        const __half* row = ten + ((long)b * HW + n) * 96 + base;
        float kv[8], vv[8];
        unpack8(*(const uint4*)(row + 8),  kv);
        unpack8(*(const uint4*)(row + 16), vv);
#pragma unroll
        for (int e = 0; e < 8; e++) kv[e] = fmaxf(kv[e], 0.f);
#pragma unroll
        for (int d = 0; d < 8; d++)
#pragma unroll
            for (int e = 0; e < 8; e++) acc[d * 8 + e] += vv[d] * kv[e];
#pragma unroll
        for (int e = 0; e < 8; e++) acc[64 + e] += kv[e];
    }

    __shared__ float red[8][72];
    int lane = threadIdx.x & 31, warp = threadIdx.x >> 5;
#pragma unroll
    for (int i = 0; i < 72; i++) {
        float v = acc[i];
#pragma unroll
        for (int off = 16; off > 0; off >>= 1) v += __shfl_xor_sync(0xffffffffu, v, off);
        if (lane == 0) red[warp][i] = v;
    }
    __syncthreads();
    if (threadIdx.x < 72) {
        float s = 0.f;
#pragma unroll
        for (int w = 0; w < 8; w++) s += red[w][threadIdx.x];
        atomicAdd(&g_vk[(b * 12 + g) * 72 + threadIdx.x], s);
    }
}

// ======================= GEMM2: proj (prefetched residual epilogue) =======================
#define P_AS      0
#define P_BS(b)   (13312 + (b) * 19968)
#define P_ST      53248
#define P_SC      78848
#define P_BI      82688
#define P_VK      86528
#define P_SMEM    89984
#define SEG2 25165824L
#define SEG3 58720256L

__global__ void __launch_bounds__(256, 2) proj_mm(
    const float* __restrict__ bn_g, const float* __restrict__ bn_b,
    const float* __restrict__ bn_m, const float* __restrict__ bn_v,
    const float* __restrict__ x1, const float* __restrict__ x2, const float* __restrict__ x3,
    float* __restrict__ out)
{
    extern __shared__ char sm[];
    uint32_t sb = smem_u32(sm);
    int tid = threadIdx.x, wid = tid >> 5, lane = tid & 31;
    int wm = wid >> 2, wn = wid & 3;
    long tok0 = (long)blockIdx.x * 64;
    int bidx = blockIdx.x >> 6;

    float* s_sc = (float*)(sm + P_SC);
    float* s_bi = (float*)(sm + P_BI);
    float* s_vk = (float*)(sm + P_VK);
    float* st   = (float*)(sm + P_ST);
    for (int c = tid; c < 960; c += 256) {
        float scv = bn_g[c] * rsqrtf(bn_v[c] + 1e-5f);
        s_sc[c] = scv;
        s_bi[c] = bn_b[c] - bn_m[c] * scv;
    }
    for (int i = tid; i < 864; i += 256) s_vk[i] = g_vk[bidx * 864 + i];
    __syncthreads();

    // fused attention -> A tile (fp16)
    {
        int tok = tid >> 2;
        int quarter = tid & 3;
        long tokG = tok0 + tok;
#pragma unroll
        for (int gg0 = 0; gg0 < 3; gg0++) {
            int gg = quarter * 3 + gg0;
            const __half* ten = (gg < 4) ? g_qkvh : (gg < 8) ? g_m3h : g_m5h;
            int base = 24 * (gg & 3);
            float q[8];
            unpack8(*(const uint4*)(ten + tokG * 96 + base), q);
#pragma unroll
            for (int e = 0; e < 8; e++) q[e] = fmaxf(q[e], 0.f);
            const float* vkp = s_vk + gg * 72;
            float den = 1e-15f;
#pragma unroll
            for (int e = 0; e < 8; e++) den += vkp[64 + e] * q[e];
            float inv = 1.0f / den;
            float o[8];
#pragma unroll
            for (int d = 0; d < 8; d++) {
                float num = 0.f;
#pragma unroll
                for (int e = 0; e < 8; e++) num += vkp[d * 8 + e] * q[e];
                o[d] = num * inv;
            }
            uint4 pack;
            pack.x = pkh(o[0], o[1]); pack.y = pkh(o[2], o[3]);
            pack.z = pkh(o[4], o[5]); pack.w = pkh(o[6], o[7]);
            *(uint4*)(sm + P_AS + (tok * 104 + gg * 8) * 2) = pack;
        }
    }

    auto cpB = [&](int t, int buf) {
        int o0 = t * 96;
#pragma unroll
        for (int p = 0; p < 5; p++) {
            int idx = tid + p * 256;
            if (idx < 1152) {
                int r = idx / 12, q = idx % 12;
                CP16(sb + P_BS(buf) + (r * 104 + q * 8) * 2, g_w2h + (long)(o0 + r) * 96 + q * 8);
            }
        }
    };
    __syncthreads();
    cpB(0, 0); CP_COMMIT();

    for (int t = 0; t < 10; t++) {
        int buf = t & 1;
        int o0 = t * 96;
        if (t + 1 < 10) { cpB(t + 1, 1 - buf); CP_COMMIT(); }
        if (t + 1 < 10) CP_WAIT1(); else CP_WAIT0();
        __syncthreads();

        // ---- prefetch residual x for THIS tile into registers (latency hidden by MMA+staging) ----
        float4 xv[6];
#pragma unroll
        for (int p = 0; p < 6; p++) {
            int idx = tid + p * 256;
            int tok = idx / 24, c4 = (idx % 24) * 4;
            long tokG = tok0 + tok;
            int chp = o0 + c4;
            const float* xp;
            if (chp < 192)      xp = x1 + tokG * 192 + chp;
            else if (chp < 448) xp = x2 + tokG * 256 + (chp - 192);
            else                xp = x3 + tokG * 512 + (chp - 448);
            xv[p] = *(const float4*)xp;
        }

        float acc[2][3][4];
#pragma unroll
        for (int i = 0; i < 2; i++)
#pragma unroll
            for (int j = 0; j < 3; j++)
#pragma unroll
                for (int k = 0; k < 4; k++) acc[i][j][k] = 0.f;

        uint32_t abase = sb + P_AS;
        uint32_t bbase = sb + P_BS(buf);
#pragma unroll
        for (int ks = 0; ks < 6; ks++) {
            uint32_t a[2][4], b[3][2];
#pragma unroll
            for (int mi = 0; mi < 2; mi++) {
                uint32_t addr = abase + ((wm * 32 + mi * 16 + (lane & 15)) * 104
                                         + ks * 16 + (lane >> 4) * 8) * 2;
                LDSM4(a[mi], addr);
            }
#pragma unroll
            for (int ni = 0; ni < 3; ni++) {
                uint32_t addr = bbase + ((wn * 24 + ni * 8 + (lane & 7)) * 104
                                         + ks * 16 + ((lane >> 3) & 1) * 8) * 2;
                LDSM2(b[ni], addr);
            }
#pragma unroll
            for (int mi = 0; mi < 2; mi++)
#pragma unroll
                for (int ni = 0; ni < 3; ni++) MMA16816(acc[mi][ni], a[mi], b[ni]);
        }

        // stage accumulators to smem [64 tok][100 pad]
#pragma unroll
        for (int mi = 0; mi < 2; mi++)
#pragma unroll
            for (int ni = 0; ni < 3; ni++)
#pragma unroll
                for (int h = 0; h < 2; h++) {
                    int tok = wm * 32 + mi * 16 + (lane >> 2) + h * 8;
                    int chl = wn * 24 + ni * 8 + (lane & 3) * 2;
                    *(float2*)(st + tok * 100 + chl) =
                        make_float2(acc[mi][ni][h*2+0], acc[mi][ni][h*2+1]);
                }
        __syncthreads();

        // combine with prefetched residual + BN, coalesced store
#pragma unroll
        for (int p = 0; p < 6; p++) {
            int idx = tid + p * 256;
            int tok = idx / 24, c4 = (idx % 24) * 4;
            long tokG = tok0 + tok;
            int chp = o0 + c4;
            float4 v  = *(const float4*)(st + tok * 100 + c4);
            float4 sc = *(const float4*)(s_sc + chp);
            float4 bi = *(const float4*)(s_bi + chp);
            float* op;
            if (chp < 192)      op = out + tokG * 192 + chp;
            else if (chp < 448) op = out + SEG2 + tokG * 256 + (chp - 192);
            else                op = out + SEG3 + tokG * 512 + (chp - 448);
            float4 o4;
            o4.x = v.x * sc.x + bi.x + xv[p].x;
            o4.y = v.y * sc.y + bi.y + xv[p].y;
            o4.z = v.z * sc.z + bi.z + xv[p].z;
            o4.w = v.w * sc.w + bi.w + xv[p].w;
            *(float4*)op = o4;
        }
        __syncthreads();
    }
}

// ======================= launch =======================
extern "C" void kernel_launch(void* const* d_in, const int* in_sizes, int n_in,
                              void* d_out, int out_size)
{
    const float *x1, *g1, *b1, *x2, *g2, *b2, *x3, *g3, *b3;
    if (in_sizes[1] < 100000) {
        x1 = (const float*)d_in[0]; g1 = (const float*)d_in[1]; b1 = (const float*)d_in[2];
        x2 = (const float*)d_in[3]; g2 = (const float*)d_in[4]; b2 = (const float*)d_in[5];
        x3 = (const float*)d_in[6]; g3 = (const float*)d_in[7]; b3 = (const float*)d_in[8];
    } else {
        x1 = (const float*)d_in[0]; x2 = (const float*)d_in[1]; x3 = (const float*)d_in[2];
        g1 = (const float*)d_in[3]; b1 = (const float*)d_in[4];
        g2 = (const float*)d_in[5]; b2 = (const float*)d_in[6];
        g3 = (const float*)d_in[7]; b3 = (const float*)d_in[8];
    }
    const float* qkv_w  = (const float*)d_in[9];
    const float* dw3    = (const float*)d_in[10];
    const float* pw3    = (const float*)d_in[11];
    const float* dw5    = (const float*)d_in[12];
    const float* pw5    = (const float*)d_in[13];
    const float* proj_w = (const float*)d_in[14];
    const float* bn_g   = (const float*)d_in[15];
    const float* bn_b   = (const float*)d_in[16];
    const float* bn_m   = (const float*)d_in[17];
    const float* bn_v   = (const float*)d_in[18];
    float* out = (float*)d_out;

    cudaFuncSetAttribute(qkv_mm,  cudaFuncAttributeMaxDynamicSharedMemorySize, G1_SMEM);
    cudaFuncSetAttribute(proj_mm, cudaFuncAttributeMaxDynamicSharedMemorySize, P_SMEM);

    lnx_kernel<<<NTOK / 8, 256>>>(x1, g1, b1, x2, g2, b2, x3, g3, b3, qkv_w, proj_w);  // 1
    qkv_mm<<<NTOK / 128, 256, G1_SMEM>>>();                                            // 2
    conv_kernel<<<dim3(4, 12, BATCH), 256>>>(dw3, pw3, dw5, pw5);                      // 3
    vk_kernel<<<dim3(12, BATCH, 4), 256>>>();                                          // 4
    proj_mm<<<NTOK / 64, 256, P_SMEM>>>(bn_g, bn_b, bn_m, bn_v, x1, x2, x3, out);      // 5
}